// round 2
// baseline (speedup 1.0000x reference)
#include <cuda_runtime.h>
#include <cuda_bf16.h>
#include <cstddef>

// Problem constants
#define S_LEN 2048
#define B_SZ  2
#define E_DIM 512
#define H_NUM 8
#define I_DIM 64
#define M_LEN 2048
#define K_LEN 4096            // M + S
#define FF_DIM 2048
#define HI 512                // H*I

// ---------------- scratch (device globals: no allocation allowed) -------------
__device__ float g_cat [K_LEN * B_SZ * E_DIM];          // (K,B,E)
__device__ float g_qkv [K_LEN * B_SZ * 3 * HI];         // (K,B,1536)
__device__ float g_r   [K_LEN * HI];                    // (K,512)
__device__ float g_attn[S_LEN * B_SZ * HI];             // (S,B,512)
__device__ float g_x1  [S_LEN * B_SZ * E_DIM];
__device__ float g_ao  [S_LEN * B_SZ * E_DIM];
__device__ float g_ffh [S_LEN * B_SZ * FF_DIM];
__device__ float g_x2  [S_LEN * B_SZ * E_DIM];

// ---------------- concat: cat = [memories; inputDec] --------------------------
__global__ void concat_kernel(const float4* __restrict__ mem,
                              const float4* __restrict__ inp,
                              float4* __restrict__ cat) {
    int idx = blockIdx.x * 256 + threadIdx.x;            // < 1048576
    const int memN = M_LEN * B_SZ * E_DIM / 4;           // 524288
    cat[idx] = (idx < memN) ? mem[idx] : inp[idx - memN];
}

// ---------------- generic SGEMM 128x128x8, 256 thr, 8x8 per thread ------------
// A: Mr x Kd row-major, B: Kd x N row-major, C: Mr x N.
// Optional bias[n], residual res[m*N+n], relu.
__global__ __launch_bounds__(256) void sgemm_kernel(
    const float* __restrict__ A, const float* __restrict__ Bm,
    float* __restrict__ C, int Mr, int N, int Kd,
    const float* __restrict__ bias, const float* __restrict__ res, int relu)
{
    __shared__ float As[8][132];
    __shared__ float Bs[8][132];
    int t  = threadIdx.x;
    int m0 = blockIdx.y * 128, n0 = blockIdx.x * 128;
    int arow = t >> 1, aseg = (t & 1) * 4;
    int brow = t >> 5, bcol = (t & 31) * 4;
    const float* Aptr = A + (size_t)(m0 + arow) * Kd + aseg;
    const float* Bptr = Bm + (size_t)brow * N + n0 + bcol;
    int ty = t >> 4, tx = t & 15;

    float acc[8][8];
#pragma unroll
    for (int i = 0; i < 8; i++)
#pragma unroll
        for (int j = 0; j < 8; j++) acc[i][j] = 0.f;

    for (int k0 = 0; k0 < Kd; k0 += 8) {
        float4 av = *(const float4*)(Aptr + k0);
        float4 bv = *(const float4*)(Bptr + (size_t)k0 * N);
        As[aseg + 0][arow] = av.x;
        As[aseg + 1][arow] = av.y;
        As[aseg + 2][arow] = av.z;
        As[aseg + 3][arow] = av.w;
        *(float4*)&Bs[brow][bcol] = bv;
        __syncthreads();
#pragma unroll
        for (int kk = 0; kk < 8; kk++) {
            float a[8], b[8];
#pragma unroll
            for (int i = 0; i < 8; i++) a[i] = As[kk][ty * 8 + i];
#pragma unroll
            for (int j = 0; j < 8; j++) b[j] = Bs[kk][tx * 8 + j];
#pragma unroll
            for (int i = 0; i < 8; i++)
#pragma unroll
                for (int j = 0; j < 8; j++) acc[i][j] += a[i] * b[j];
        }
        __syncthreads();
    }

#pragma unroll
    for (int i = 0; i < 8; i++) {
        int m = m0 + ty * 8 + i;
#pragma unroll
        for (int j = 0; j < 8; j++) {
            int n = n0 + tx * 8 + j;
            float vv = acc[i][j];
            if (bias) vv += bias[n];
            if (res)  vv += res[(size_t)m * N + n];
            if (relu) vv = fmaxf(vv, 0.f);
            C[(size_t)m * N + n] = vv;
        }
    }
}

// ---------------- fused flash attention with TXL relative position -------------
// score[s,k] = ((q[s]+u)·kk[k] + (q[s]+v)·r[k-s+2047]) / 8, valid iff k <= s+2048
// grid: (S/64, H, B); block 256 (16x16); each thread: 4x4 scores, 4x4 output.
#define AT_SMEM_FLOATS (4 * 65 * 64 + 129 * 64 + 128)
__global__ __launch_bounds__(256) void attn_kernel(
    const float* __restrict__ qkv, const float* __restrict__ rbuf,
    const float* __restrict__ u, const float* __restrict__ v,
    float* __restrict__ attn)
{
    extern __shared__ float sm[];
    float* qT  = sm;               // [i][sq]  stride 65
    float* kkT = qT  + 65 * 64;    // [i][kq]  stride 65
    float* Vs  = kkT + 65 * 64;    // [kq][iv] stride 65
    float* Ps  = Vs  + 65 * 64;    // [sq][kq] stride 65
    float* rrT = Ps  + 65 * 64;    // [i][d]   stride 129, d in [0,128)
    float* us  = rrT + 129 * 64;
    float* vs  = us + 64;

    int t  = threadIdx.x;
    int s0 = blockIdx.x * 64;
    int h  = blockIdx.y;
    int bb = blockIdx.z;
    int tx = t & 15, ty = t >> 4;

    // q tile (i-major) + u/v rows
    for (int idx = t; idx < 4096; idx += 256) {
        int sq = idx >> 6, i = idx & 63;
        qT[i * 65 + sq] =
            qkv[((size_t)(M_LEN + s0 + sq) * B_SZ + bb) * 1536 + h * 64 + i];
    }
    if (t < 64) { us[t] = u[h * 64 + t]; vs[t] = v[h * 64 + t]; }

    float m_[4], l_[4], acc[4][4];
#pragma unroll
    for (int r4 = 0; r4 < 4; r4++) {
        m_[r4] = -1e30f; l_[r4] = 0.f;
#pragma unroll
        for (int c4 = 0; c4 < 4; c4++) acc[r4][c4] = 0.f;
    }

    int nk = (s0 + 63 + M_LEN) / 64 + 1;   // key tiles covering k <= s0+63+M

    for (int kt = 0; kt < nk; kt++) {
        int k0 = kt * 64;
        int jbase = k0 - s0 + 1984;        // j = jbase + d, d = kq - sq + 63

        for (int idx = t; idx < 4096; idx += 256) {
            int kq = idx >> 6, i = idx & 63;
            size_t base = ((size_t)(k0 + kq) * B_SZ + bb) * 1536 + h * 64;
            kkT[i * 65 + kq] = qkv[base + 512  + i];
            Vs[kq * 65 + i]  = qkv[base + 1024 + i];
        }
        for (int idx = t; idx < 8192; idx += 256) {
            int d = idx >> 6, i = idx & 63;
            int j = jbase + d;             // j >= 0 guaranteed
            rrT[i * 129 + d] = (j < K_LEN) ? rbuf[(size_t)j * HI + h * 64 + i] : 0.f;
        }
        __syncthreads();

        float sc[4][4];
#pragma unroll
        for (int r4 = 0; r4 < 4; r4++)
#pragma unroll
            for (int c4 = 0; c4 < 4; c4++) sc[r4][c4] = 0.f;

#pragma unroll 4
        for (int i = 0; i < 64; i++) {
            float ui = us[i], vi = vs[i];
            float q4[4], k4[4], r7[7];
#pragma unroll
            for (int r4 = 0; r4 < 4; r4++) q4[r4] = qT[i * 65 + ty + 16 * r4];
#pragma unroll
            for (int c4 = 0; c4 < 4; c4++) k4[c4] = kkT[i * 65 + tx + 16 * c4];
#pragma unroll
            for (int c7 = 0; c7 < 7; c7++)
                r7[c7] = rrT[i * 129 + (tx - ty + 15 + 16 * c7)];
#pragma unroll
            for (int r4 = 0; r4 < 4; r4++) {
                float a1 = q4[r4] + ui;
                float a2 = q4[r4] + vi;
#pragma unroll
                for (int c4 = 0; c4 < 4; c4++)
                    sc[r4][c4] += a1 * k4[c4] + a2 * r7[c4 - r4 + 3];
            }
        }

        // scale + mask
#pragma unroll
        for (int r4 = 0; r4 < 4; r4++) {
            int srow = s0 + ty + 16 * r4;
#pragma unroll
            for (int c4 = 0; c4 < 4; c4++) {
                int kcol = k0 + tx + 16 * c4;
                float val = sc[r4][c4] * 0.125f;
                sc[r4][c4] = (kcol <= srow + M_LEN) ? val : -1e30f;
            }
        }

        // online softmax update (rows split across 16 lanes of a warp half)
#pragma unroll
        for (int r4 = 0; r4 < 4; r4++) {
            float mx = fmaxf(fmaxf(sc[r4][0], sc[r4][1]), fmaxf(sc[r4][2], sc[r4][3]));
#pragma unroll
            for (int o = 8; o >= 1; o >>= 1)
                mx = fmaxf(mx, __shfl_xor_sync(0xffffffffu, mx, o));
            float mn = fmaxf(m_[r4], mx);
            float corr = __expf(m_[r4] - mn);
            float psum = 0.f;
#pragma unroll
            for (int c4 = 0; c4 < 4; c4++) {
                float p = __expf(sc[r4][c4] - mn);
                sc[r4][c4] = p; psum += p;
            }
#pragma unroll
            for (int o = 8; o >= 1; o >>= 1)
                psum += __shfl_xor_sync(0xffffffffu, psum, o);
            l_[r4] = l_[r4] * corr + psum;
            m_[r4] = mn;
#pragma unroll
            for (int c4 = 0; c4 < 4; c4++) {
                acc[r4][c4] *= corr;
                Ps[(ty + 16 * r4) * 65 + tx + 16 * c4] = sc[r4][c4];
            }
        }
        __syncthreads();

        // PV accumulate
#pragma unroll 4
        for (int kq = 0; kq < 64; kq++) {
            float vr[4];
#pragma unroll
            for (int c4 = 0; c4 < 4; c4++) vr[c4] = Vs[kq * 65 + tx + 16 * c4];
#pragma unroll
            for (int r4 = 0; r4 < 4; r4++) {
                float p = Ps[(ty + 16 * r4) * 65 + kq];
#pragma unroll
                for (int c4 = 0; c4 < 4; c4++) acc[r4][c4] += p * vr[c4];
            }
        }
        __syncthreads();
    }

#pragma unroll
    for (int r4 = 0; r4 < 4; r4++) {
        float inv = 1.f / l_[r4];
        int srow = s0 + ty + 16 * r4;
#pragma unroll
        for (int c4 = 0; c4 < 4; c4++)
            attn[((size_t)srow * B_SZ + bb) * HI + h * 64 + tx + 16 * c4] =
                acc[r4][c4] * inv;
    }
}

// ---------------- layernorm over last dim (512), one block per row ------------
__global__ __launch_bounds__(256) void ln_kernel(
    const float* __restrict__ x, const float* __restrict__ g,
    const float* __restrict__ beta, float* __restrict__ y)
{
    __shared__ float sbuf[256];
    int row = blockIdx.x;
    int t = threadIdx.x;
    const float* xr = x + (size_t)row * E_DIM;
    float v0 = xr[t], v1 = xr[t + 256];

    sbuf[t] = v0 + v1;
    __syncthreads();
    for (int o = 128; o > 0; o >>= 1) {
        if (t < o) sbuf[t] += sbuf[t + o];
        __syncthreads();
    }
    float mu = sbuf[0] * (1.f / E_DIM);
    __syncthreads();

    float d0 = v0 - mu, d1 = v1 - mu;
    sbuf[t] = d0 * d0 + d1 * d1;
    __syncthreads();
    for (int o = 128; o > 0; o >>= 1) {
        if (t < o) sbuf[t] += sbuf[t + o];
        __syncthreads();
    }
    float rstd = rsqrtf(sbuf[0] * (1.f / E_DIM) + 1e-5f);

    float* yr = y + (size_t)row * E_DIM;
    yr[t]       = d0 * rstd * g[t]       + beta[t];
    yr[t + 256] = d1 * rstd * g[t + 256] + beta[t + 256];
}

// -------------------------------- launch --------------------------------------
extern "C" void kernel_launch(void* const* d_in, const int* in_sizes, int n_in,
                              void* d_out, int out_size) {
    (void)in_sizes; (void)n_in; (void)out_size;
    const float* inputDec = (const float*)d_in[0];
    const float* posEmb   = (const float*)d_in[1];
    const float* u        = (const float*)d_in[2];
    const float* v        = (const float*)d_in[3];
    const float* memories = (const float*)d_in[4];
    const float* Wqkv     = (const float*)d_in[5];
    const float* Wr       = (const float*)d_in[6];
    const float* Wo       = (const float*)d_in[7];
    const float* ln1g     = (const float*)d_in[8];
    const float* ln1b     = (const float*)d_in[9];
    const float* W1       = (const float*)d_in[10];
    const float* b1       = (const float*)d_in[11];
    const float* W2       = (const float*)d_in[12];
    const float* b2       = (const float*)d_in[13];
    const float* ln2g     = (const float*)d_in[14];
    const float* ln2b     = (const float*)d_in[15];
    float* out = (float*)d_out;

    float *cat, *qkv, *rb, *attn, *x1, *ao, *ffh, *x2;
    cudaGetSymbolAddress((void**)&cat,  g_cat);
    cudaGetSymbolAddress((void**)&qkv,  g_qkv);
    cudaGetSymbolAddress((void**)&rb,   g_r);
    cudaGetSymbolAddress((void**)&attn, g_attn);
    cudaGetSymbolAddress((void**)&x1,   g_x1);
    cudaGetSymbolAddress((void**)&ao,   g_ao);
    cudaGetSymbolAddress((void**)&ffh,  g_ffh);
    cudaGetSymbolAddress((void**)&x2,   g_x2);

    int atSmem = AT_SMEM_FLOATS * (int)sizeof(float);   // 100096 bytes
    cudaFuncSetAttribute(attn_kernel,
                         cudaFuncAttributeMaxDynamicSharedMemorySize, atSmem);

    // 1. concat
    concat_kernel<<<K_LEN * B_SZ * E_DIM / 4 / 256, 256>>>(
        (const float4*)memories, (const float4*)inputDec, (float4*)cat);

    // 2. qkv = cat @ Wqkv   (8192 x 1536 x 512)
    sgemm_kernel<<<dim3(1536 / 128, (K_LEN * B_SZ) / 128), 256>>>(
        cat, Wqkv, qkv, K_LEN * B_SZ, 1536, E_DIM, nullptr, nullptr, 0);

    // 3. r = posEmb @ Wr    (4096 x 512 x 512)
    sgemm_kernel<<<dim3(HI / 128, K_LEN / 128), 256>>>(
        posEmb, Wr, rb, K_LEN, HI, E_DIM, nullptr, nullptr, 0);

    // 4. fused attention
    attn_kernel<<<dim3(S_LEN / 64, H_NUM, B_SZ), 256, atSmem>>>(qkv, rb, u, v, attn);

    // 5. x1 = attn @ Wo + inputDec  (4096 x 512 x 512)
    sgemm_kernel<<<dim3(E_DIM / 128, (S_LEN * B_SZ) / 128), 256>>>(
        attn, Wo, x1, S_LEN * B_SZ, E_DIM, HI, nullptr, inputDec, 0);

    // 6. attn_out = LN1(x1)
    ln_kernel<<<S_LEN * B_SZ, 256>>>(x1, ln1g, ln1b, ao);

    // 7. ffh = relu(attn_out @ W1 + b1)  (4096 x 2048 x 512)
    sgemm_kernel<<<dim3(FF_DIM / 128, (S_LEN * B_SZ) / 128), 256>>>(
        ao, W1, ffh, S_LEN * B_SZ, FF_DIM, E_DIM, b1, nullptr, 1);

    // 8. x2 = ffh @ W2 + b2 + attn_out  (4096 x 512 x 2048)
    sgemm_kernel<<<dim3(E_DIM / 128, (S_LEN * B_SZ) / 128), 256>>>(
        ffh, W2, x2, S_LEN * B_SZ, E_DIM, FF_DIM, b2, ao, 0);

    // 9. out = LN2(x2)
    ln_kernel<<<S_LEN * B_SZ, 256>>>(x2, ln2g, ln2b, out);
}

// round 7
// speedup vs baseline: 1.3458x; 1.3458x over previous
#include <cuda_runtime.h>
#include <cuda_bf16.h>
#include <cstdint>
#include <cstddef>

// Problem constants
#define S_LEN 2048
#define B_SZ  2
#define E_DIM 512
#define H_NUM 8
#define I_DIM 64
#define M_LEN 2048
#define K_LEN 4096            // M + S
#define FF_DIM 2048
#define HI 512                // H*I

// ---------------- scratch (device globals: no allocation allowed) -------------
__device__ float g_cat [K_LEN * B_SZ * E_DIM];          // (K,B,E)
__device__ float g_qkv [K_LEN * B_SZ * 3 * HI];         // (K,B,1536)
__device__ float g_r   [K_LEN * HI];                    // (K,512)
__device__ float g_attn[S_LEN * B_SZ * HI];             // (S,B,512)
__device__ float g_x1  [S_LEN * B_SZ * E_DIM];
__device__ float g_ao  [S_LEN * B_SZ * E_DIM];
__device__ float g_ffh [S_LEN * B_SZ * FF_DIM];
__device__ float g_x2  [S_LEN * B_SZ * E_DIM];

// ---------------- concat: cat = [memories; inputDec] --------------------------
__global__ void concat_kernel(const float4* __restrict__ mem,
                              const float4* __restrict__ inp,
                              float4* __restrict__ cat) {
    int idx = blockIdx.x * 256 + threadIdx.x;            // < 1048576
    const int memN = M_LEN * B_SZ * E_DIM / 4;           // 524288
    cat[idx] = (idx < memN) ? mem[idx] : inp[idx - memN];
}

// ---------------- tf32 tensor-core GEMM 128x128, k-step 16 --------------------
// C[MrxN] = A[MrxKd] @ B[KdxN] (+bias, +res, relu). mma.m16n8k8 tf32.
__device__ __forceinline__ uint32_t f2tf32(float f) {
    uint32_t u;
    asm("cvt.rna.tf32.f32 %0, %1;" : "=r"(u) : "f"(f));
    return u;
}

#define AS_STRIDE 20          // [m 0..127][k 0..15], stride 20 (conflict-free frags)
#define BS_STRIDE 136         // [k 0..15][n 0..127], stride 136 (conflict-free frags)

__global__ __launch_bounds__(256) void tgemm_kernel(
    const float* __restrict__ A, const float* __restrict__ Bm,
    float* __restrict__ C, int Mr, int N, int Kd,
    const float* __restrict__ bias, const float* __restrict__ res, int relu)
{
    __shared__ uint32_t As[128 * AS_STRIDE];
    __shared__ uint32_t Bs[16 * BS_STRIDE];

    int t    = threadIdx.x;
    int warp = t >> 5, lane = t & 31;
    int wm   = warp >> 2;          // 0..1 -> 64 rows each
    int wn   = warp & 3;           // 0..3 -> 32 cols each
    int g    = lane >> 2;          // 0..7
    int tg   = lane & 3;           // 0..3
    int m0 = blockIdx.y * 128, n0 = blockIdx.x * 128;

    float acc[4][4][4];
#pragma unroll
    for (int mf = 0; mf < 4; mf++)
#pragma unroll
        for (int nf = 0; nf < 4; nf++)
#pragma unroll
            for (int c = 0; c < 4; c++) acc[mf][nf][c] = 0.f;

    // global-load mapping (per 16-k step):
    // A: 128 rows x 16 k = 512 float4 -> 2 per thread
    int arow0 = t >> 2, aks = (t & 3) * 4;        // +64 rows for rep 1
    // B: 16 rows x 128 n = 512 float4 -> 2 per thread
    int brow0 = t >> 5, bns = (t & 31) * 4;       // +8 rows for rep 1

    for (int k0 = 0; k0 < Kd; k0 += 16) {
#pragma unroll
        for (int rep = 0; rep < 2; rep++) {
            int arow = arow0 + rep * 64;
            float4 av = *(const float4*)(A + (size_t)(m0 + arow) * Kd + k0 + aks);
            uint32_t* ap = &As[arow * AS_STRIDE + aks];
            ap[0] = f2tf32(av.x); ap[1] = f2tf32(av.y);
            ap[2] = f2tf32(av.z); ap[3] = f2tf32(av.w);

            int brow = brow0 + rep * 8;
            float4 bv = *(const float4*)(Bm + (size_t)(k0 + brow) * N + n0 + bns);
            uint32_t* bp = &Bs[brow * BS_STRIDE + bns];
            bp[0] = f2tf32(bv.x); bp[1] = f2tf32(bv.y);
            bp[2] = f2tf32(bv.z); bp[3] = f2tf32(bv.w);
        }
        __syncthreads();

#pragma unroll
        for (int kk = 0; kk < 16; kk += 8) {
            uint32_t a[4][4], b[4][2];
#pragma unroll
            for (int mf = 0; mf < 4; mf++) {
                int base = (wm * 64 + mf * 16 + g) * AS_STRIDE + kk + tg;
                a[mf][0] = As[base];
                a[mf][1] = As[base + 8 * AS_STRIDE];
                a[mf][2] = As[base + 4];
                a[mf][3] = As[base + 8 * AS_STRIDE + 4];
            }
#pragma unroll
            for (int nf = 0; nf < 4; nf++) {
                int col = wn * 32 + nf * 8 + g;
                b[nf][0] = Bs[(kk + tg) * BS_STRIDE + col];
                b[nf][1] = Bs[(kk + tg + 4) * BS_STRIDE + col];
            }
#pragma unroll
            for (int mf = 0; mf < 4; mf++)
#pragma unroll
                for (int nf = 0; nf < 4; nf++) {
                    float* d = acc[mf][nf];
                    asm volatile(
                        "mma.sync.aligned.m16n8k8.row.col.f32.tf32.tf32.f32 "
                        "{%0,%1,%2,%3}, {%4,%5,%6,%7}, {%8,%9}, {%0,%1,%2,%3};"
                        : "+f"(d[0]), "+f"(d[1]), "+f"(d[2]), "+f"(d[3])
                        : "r"(a[mf][0]), "r"(a[mf][1]), "r"(a[mf][2]), "r"(a[mf][3]),
                          "r"(b[nf][0]), "r"(b[nf][1]));
                }
        }
        __syncthreads();
    }

    // epilogue: c0,c1 -> (row, col..col+1); c2,c3 -> (row+8, ...)
#pragma unroll
    for (int mf = 0; mf < 4; mf++) {
#pragma unroll
        for (int nf = 0; nf < 4; nf++) {
            int row = m0 + wm * 64 + mf * 16 + g;
            int col = n0 + wn * 32 + nf * 8 + 2 * tg;
            float b0 = 0.f, b1 = 0.f;
            if (bias) { b0 = bias[col]; b1 = bias[col + 1]; }
#pragma unroll
            for (int half = 0; half < 2; half++) {
                int r = row + half * 8;
                float v0 = acc[mf][nf][2 * half]     + b0;
                float v1 = acc[mf][nf][2 * half + 1] + b1;
                if (res) {
                    v0 += res[(size_t)r * N + col];
                    v1 += res[(size_t)r * N + col + 1];
                }
                if (relu) { v0 = fmaxf(v0, 0.f); v1 = fmaxf(v1, 0.f); }
                float2 vv = make_float2(v0, v1);
                *(float2*)(C + (size_t)r * N + col) = vv;
            }
        }
    }
}

// ---------------- fused flash attention with TXL relative position -------------
// score[s,k] = ((q[s]+u)·kk[k] + (q[s]+v)·r[k-s+2047]) / 8, valid iff k <= s+2048
// grid: (S/64, H, B); block 256 (16x16); each thread: contiguous 4x4 block.
#define QS 68                  // stride for qT/kkT/Vs/Ps
#define RS 132                 // stride for rrT
#define AT_SMEM_FLOATS (4 * QS * 64 + RS * 64 + 128)
__global__ __launch_bounds__(256) void attn_kernel(
    const float* __restrict__ qkv, const float* __restrict__ rbuf,
    const float* __restrict__ u, const float* __restrict__ v,
    float* __restrict__ attn)
{
    extern __shared__ float sm[];
    float* qT  = sm;               // [i][sq]  stride QS
    float* kkT = qT  + QS * 64;    // [i][kq]  stride QS
    float* Vs  = kkT + QS * 64;    // [kq][i]  stride QS
    float* Ps  = Vs  + QS * 64;    // [sq][kq] stride QS
    float* rrT = Ps  + QS * 64;    // [i][d]   stride RS, d in [0,128)
    float* us  = rrT + RS * 64;
    float* vs  = us + 64;

    int t  = threadIdx.x;
    int s0 = blockIdx.x * 64;
    int h  = blockIdx.y;
    int bb = blockIdx.z;
    int tx = t & 15, ty = t >> 4;       // thread block of rows 4ty.., cols 4tx..
    int dbase = 4 * (tx - ty) + 60;     // float4-aligned r-window base

    // q tile (i-major, transposed store) + u/v rows
    for (int idx = t; idx < 1024; idx += 256) {
        int i4 = idx >> 6, sq = idx & 63;
        float4 qv = *(const float4*)&qkv[((size_t)(M_LEN + s0 + sq) * B_SZ + bb) * 1536
                                         + h * 64 + 4 * i4];
        qT[(4 * i4 + 0) * QS + sq] = qv.x;
        qT[(4 * i4 + 1) * QS + sq] = qv.y;
        qT[(4 * i4 + 2) * QS + sq] = qv.z;
        qT[(4 * i4 + 3) * QS + sq] = qv.w;
    }
    if (t < 64) { us[t] = u[h * 64 + t]; vs[t] = v[h * 64 + t]; }

    float m_[4], l_[4], acc[4][4];
#pragma unroll
    for (int r = 0; r < 4; r++) {
        m_[r] = -1e30f; l_[r] = 0.f;
#pragma unroll
        for (int c = 0; c < 4; c++) acc[r][c] = 0.f;
    }

    int nk = (s0 + 63 + M_LEN) / 64 + 1;   // key tiles covering k <= s0+63+M

    for (int kt = 0; kt < nk; kt++) {
        int k0 = kt * 64;
        int jbase = k0 - s0 + 1984;        // j = jbase + d

        for (int idx = t; idx < 1024; idx += 256) {
            int i4 = idx >> 6, kq = idx & 63;
            size_t base = ((size_t)(k0 + kq) * B_SZ + bb) * 1536 + h * 64 + 4 * i4;
            float4 kv = *(const float4*)&qkv[base + 512];
            kkT[(4 * i4 + 0) * QS + kq] = kv.x;
            kkT[(4 * i4 + 1) * QS + kq] = kv.y;
            kkT[(4 * i4 + 2) * QS + kq] = kv.z;
            kkT[(4 * i4 + 3) * QS + kq] = kv.w;
            float4 vv = *(const float4*)&qkv[base + 1024];
            *(float4*)&Vs[kq * QS + 4 * i4] = vv;
        }
        for (int idx = t; idx < 2048; idx += 256) {
            int i4 = idx >> 7, d = idx & 127;
            int j = jbase + d;             // j >= 0 guaranteed
            float4 rv = make_float4(0.f, 0.f, 0.f, 0.f);
            if (j < K_LEN)
                rv = *(const float4*)&rbuf[(size_t)j * HI + h * 64 + 4 * i4];
            rrT[(4 * i4 + 0) * RS + d] = rv.x;
            rrT[(4 * i4 + 1) * RS + d] = rv.y;
            rrT[(4 * i4 + 2) * RS + d] = rv.z;
            rrT[(4 * i4 + 3) * RS + d] = rv.w;
        }
        __syncthreads();

        float sc[4][4];
#pragma unroll
        for (int r = 0; r < 4; r++)
#pragma unroll
            for (int c = 0; c < 4; c++) sc[r][c] = 0.f;

        const float4* qp = (const float4*)&qT[4 * ty];
        const float4* kp = (const float4*)&kkT[4 * tx];
        const float4* rp = (const float4*)&rrT[dbase];

#pragma unroll 4
        for (int i = 0; i < 64; i++) {
            float4 qv = qp[i * (QS / 4)];
            float4 kv = kp[i * (QS / 4)];
            float4 r0 = rp[i * (RS / 4)];
            float4 r1 = rp[i * (RS / 4) + 1];
            float ui = us[i], vi = vs[i];
            float q4[4] = {qv.x, qv.y, qv.z, qv.w};
            float k4[4] = {kv.x, kv.y, kv.z, kv.w};
            float rw[8] = {r0.x, r0.y, r0.z, r0.w, r1.x, r1.y, r1.z, r1.w};
#pragma unroll
            for (int r = 0; r < 4; r++) {
                float a1 = q4[r] + ui;
                float a2 = q4[r] + vi;
#pragma unroll
                for (int c = 0; c < 4; c++)
                    sc[r][c] += a1 * k4[c] + a2 * rw[c - r + 3];
            }
        }

        // scale + mask
#pragma unroll
        for (int r = 0; r < 4; r++) {
            int srow = s0 + 4 * ty + r;
#pragma unroll
            for (int c = 0; c < 4; c++) {
                int kcol = k0 + 4 * tx + c;
                float val = sc[r][c] * 0.125f;
                sc[r][c] = (kcol <= srow + M_LEN) ? val : -1e30f;
            }
        }

        // online softmax (row owners = 16 lanes sharing ty within the warp)
#pragma unroll
        for (int r = 0; r < 4; r++) {
            float mx = fmaxf(fmaxf(sc[r][0], sc[r][1]), fmaxf(sc[r][2], sc[r][3]));
#pragma unroll
            for (int o = 8; o >= 1; o >>= 1)
                mx = fmaxf(mx, __shfl_xor_sync(0xffffffffu, mx, o));
            float mn = fmaxf(m_[r], mx);
            float corr = __expf(m_[r] - mn);
            float psum = 0.f;
#pragma unroll
            for (int c = 0; c < 4; c++) {
                float p = __expf(sc[r][c] - mn);
                sc[r][c] = p; psum += p;
            }
#pragma unroll
            for (int o = 8; o >= 1; o >>= 1)
                psum += __shfl_xor_sync(0xffffffffu, psum, o);
            l_[r] = l_[r] * corr + psum;
            m_[r] = mn;
#pragma unroll
            for (int c = 0; c < 4; c++) acc[r][c] *= corr;
            *(float4*)&Ps[(4 * ty + r) * QS + 4 * tx] =
                make_float4(sc[r][0], sc[r][1], sc[r][2], sc[r][3]);
        }
        __syncthreads();

        // PV accumulate in 4-key chunks (all float4 LDS)
#pragma unroll 2
        for (int kq0 = 0; kq0 < 64; kq0 += 4) {
            float vm[4][4];
#pragma unroll
            for (int j = 0; j < 4; j++) {
                float4 vv = *(const float4*)&Vs[(kq0 + j) * QS + 4 * tx];
                vm[j][0] = vv.x; vm[j][1] = vv.y; vm[j][2] = vv.z; vm[j][3] = vv.w;
            }
#pragma unroll
            for (int r = 0; r < 4; r++) {
                float4 p = *(const float4*)&Ps[(4 * ty + r) * QS + kq0];
                float pr[4] = {p.x, p.y, p.z, p.w};
#pragma unroll
                for (int c = 0; c < 4; c++)
                    acc[r][c] += pr[0] * vm[0][c] + pr[1] * vm[1][c]
                               + pr[2] * vm[2][c] + pr[3] * vm[3][c];
            }
        }
        __syncthreads();
    }

#pragma unroll
    for (int r = 0; r < 4; r++) {
        float inv = 1.f / l_[r];
        int srow = s0 + 4 * ty + r;
        float4 ov = make_float4(acc[r][0] * inv, acc[r][1] * inv,
                                acc[r][2] * inv, acc[r][3] * inv);
        *(float4*)&attn[((size_t)srow * B_SZ + bb) * HI + h * 64 + 4 * tx] = ov;
    }
}

// ---------------- layernorm over last dim (512), one block per row ------------
__global__ __launch_bounds__(256) void ln_kernel(
    const float* __restrict__ x, const float* __restrict__ g,
    const float* __restrict__ beta, float* __restrict__ y)
{
    __shared__ float sbuf[256];
    int row = blockIdx.x;
    int t = threadIdx.x;
    const float* xr = x + (size_t)row * E_DIM;
    float v0 = xr[t], v1 = xr[t + 256];

    sbuf[t] = v0 + v1;
    __syncthreads();
    for (int o = 128; o > 0; o >>= 1) {
        if (t < o) sbuf[t] += sbuf[t + o];
        __syncthreads();
    }
    float mu = sbuf[0] * (1.f / E_DIM);
    __syncthreads();

    float d0 = v0 - mu, d1 = v1 - mu;
    sbuf[t] = d0 * d0 + d1 * d1;
    __syncthreads();
    for (int o = 128; o > 0; o >>= 1) {
        if (t < o) sbuf[t] += sbuf[t + o];
        __syncthreads();
    }
    float rstd = rsqrtf(sbuf[0] * (1.f / E_DIM) + 1e-5f);

    float* yr = y + (size_t)row * E_DIM;
    yr[t]       = d0 * rstd * g[t]       + beta[t];
    yr[t + 256] = d1 * rstd * g[t + 256] + beta[t + 256];
}

// -------------------------------- launch --------------------------------------
extern "C" void kernel_launch(void* const* d_in, const int* in_sizes, int n_in,
                              void* d_out, int out_size) {
    (void)in_sizes; (void)n_in; (void)out_size;
    const float* inputDec = (const float*)d_in[0];
    const float* posEmb   = (const float*)d_in[1];
    const float* u        = (const float*)d_in[2];
    const float* v        = (const float*)d_in[3];
    const float* memories = (const float*)d_in[4];
    const float* Wqkv     = (const float*)d_in[5];
    const float* Wr       = (const float*)d_in[6];
    const float* Wo       = (const float*)d_in[7];
    const float* ln1g     = (const float*)d_in[8];
    const float* ln1b     = (const float*)d_in[9];
    const float* W1       = (const float*)d_in[10];
    const float* b1       = (const float*)d_in[11];
    const float* W2       = (const float*)d_in[12];
    const float* b2       = (const float*)d_in[13];
    const float* ln2g     = (const float*)d_in[14];
    const float* ln2b     = (const float*)d_in[15];
    float* out = (float*)d_out;

    float *cat, *qkv, *rb, *attn, *x1, *ao, *ffh, *x2;
    cudaGetSymbolAddress((void**)&cat,  g_cat);
    cudaGetSymbolAddress((void**)&qkv,  g_qkv);
    cudaGetSymbolAddress((void**)&rb,   g_r);
    cudaGetSymbolAddress((void**)&attn, g_attn);
    cudaGetSymbolAddress((void**)&x1,   g_x1);
    cudaGetSymbolAddress((void**)&ao,   g_ao);
    cudaGetSymbolAddress((void**)&ffh,  g_ffh);
    cudaGetSymbolAddress((void**)&x2,   g_x2);

    int atSmem = AT_SMEM_FLOATS * (int)sizeof(float);   // ~104 KB
    cudaFuncSetAttribute(attn_kernel,
                         cudaFuncAttributeMaxDynamicSharedMemorySize, atSmem);

    // 1. concat
    concat_kernel<<<K_LEN * B_SZ * E_DIM / 4 / 256, 256>>>(
        (const float4*)memories, (const float4*)inputDec, (float4*)cat);

    // 2. qkv = cat @ Wqkv   (8192 x 1536 x 512)
    tgemm_kernel<<<dim3(1536 / 128, (K_LEN * B_SZ) / 128), 256>>>(
        cat, Wqkv, qkv, K_LEN * B_SZ, 1536, E_DIM, nullptr, nullptr, 0);

    // 3. r = posEmb @ Wr    (4096 x 512 x 512)
    tgemm_kernel<<<dim3(HI / 128, K_LEN / 128), 256>>>(
        posEmb, Wr, rb, K_LEN, HI, E_DIM, nullptr, nullptr, 0);

    // 4. fused attention
    attn_kernel<<<dim3(S_LEN / 64, H_NUM, B_SZ), 256, atSmem>>>(qkv, rb, u, v, attn);

    // 5. x1 = attn @ Wo + inputDec  (4096 x 512 x 512)
    tgemm_kernel<<<dim3(E_DIM / 128, (S_LEN * B_SZ) / 128), 256>>>(
        attn, Wo, x1, S_LEN * B_SZ, E_DIM, HI, nullptr, inputDec, 0);

    // 6. attn_out = LN1(x1)
    ln_kernel<<<S_LEN * B_SZ, 256>>>(x1, ln1g, ln1b, ao);

    // 7. ffh = relu(attn_out @ W1 + b1)  (4096 x 2048 x 512)
    tgemm_kernel<<<dim3(FF_DIM / 128, (S_LEN * B_SZ) / 128), 256>>>(
        ao, W1, ffh, S_LEN * B_SZ, FF_DIM, E_DIM, b1, nullptr, 1);

    // 8. x2 = ffh @ W2 + b2 + attn_out  (4096 x 512 x 2048)
    tgemm_kernel<<<dim3(E_DIM / 128, (S_LEN * B_SZ) / 128), 256>>>(
        ffh, W2, x2, S_LEN * B_SZ, E_DIM, FF_DIM, b2, ao, 0);

    // 9. out = LN2(x2)
    ln_kernel<<<S_LEN * B_SZ, 256>>>(x2, ln2g, ln2b, out);
}